// round 5
// baseline (speedup 1.0000x reference)
#include <cuda_runtime.h>
#include <cuda_fp16.h>

// Problem constants (from reference): N=50000, DIM=64, HEADS=4, E=800000.
#define MAXN 50000
#define MAXE 800000
#define MAXET (MAXE + MAXN)
#define HC 256   // HEADS * DIM

// ---------------- scratch (static device globals; no allocation) ----------------
__device__ __align__(16) __half g_xh[MAXN * HC];      // [N, H, C] = x @ W  (fp16)
__device__ __align__(16) float g_asrc[MAXN * 4];      // [N, H]
__device__ __align__(16) float g_adst[MAXN * 4];      // [N, H]
__device__ int    g_deg[MAXN];
__device__ int    g_off[MAXN + 1];
__device__ int    g_bsum[64];
__device__ int    g_boff[64];
__device__ int    g_rank[MAXET];                      // within-dst rank of each edge
__device__ float4 g_pack[MAXET];                      // CSR rec: {src:int, exp01:h2, exp23:h2, pad}
__device__ int    g_is64;                             // 1 if edge buffer is int64

// ---------------- detect int32 vs int64 edge buffer ----------------
__global__ void detect_kernel(const int* __restrict__ e32) {
    __shared__ int s_any;
    if (threadIdx.x == 0) s_any = 0;
    __syncthreads();
    int any = 0;
    for (int i = threadIdx.x; i < 2048; i += blockDim.x)
        any |= e32[2 * i + 1];
    if (any) atomicOr(&s_any, 1);
    __syncthreads();
    if (threadIdx.x == 0) g_is64 = s_any ? 0 : 1;
}

// ---------------- init counters ----------------
__global__ void init_kernel(int N) {
    int i = blockIdx.x * blockDim.x + threadIdx.x;
    if (i < N) g_deg[i] = 0;
}

// ---------------- GEMM g_xh[N,256] = X[N,64] @ W[64,256]  + fused a_src/a_dst ----------------
__global__ void gemm_kernel(const float* __restrict__ X, const float* __restrict__ W,
                            const float* __restrict__ att_src,
                            const float* __restrict__ att_dst, int N) {
    __shared__ float sx[64][65];
    __shared__ float sw[64][65];
    int row0 = blockIdx.x * 64;
    int hy   = blockIdx.y;          // head
    int col0 = hy * 64;
    int t = threadIdx.x;            // 256 threads

    #pragma unroll
    for (int i = t; i < 64 * 64; i += 256) {
        int k = i >> 6, j = i & 63;
        sw[k][j] = W[k * 256 + col0 + j];
    }
    #pragma unroll
    for (int i = t; i < 64 * 64; i += 256) {
        int r = i >> 6, k = i & 63;
        int row = row0 + r;
        sx[r][k] = (row < N) ? X[row * 64 + k] : 0.0f;
    }
    __syncthreads();

    int tx = t & 15, ty = t >> 4;
    int r0 = ty * 4, c0 = tx * 4;
    float acc[4][4] = {};
    #pragma unroll
    for (int k = 0; k < 64; k++) {
        float b0 = sw[k][c0 + 0], b1 = sw[k][c0 + 1];
        float b2 = sw[k][c0 + 2], b3 = sw[k][c0 + 3];
        #pragma unroll
        for (int i = 0; i < 4; i++) {
            float a = sx[r0 + i][k];
            acc[i][0] += a * b0; acc[i][1] += a * b1;
            acc[i][2] += a * b2; acc[i][3] += a * b3;
        }
    }

    // store fp16 features
    #pragma unroll
    for (int i = 0; i < 4; i++) {
        int row = row0 + r0 + i;
        if (row < N) {
            __half2 h01 = __floats2half2_rn(acc[i][0], acc[i][1]);
            __half2 h23 = __floats2half2_rn(acc[i][2], acc[i][3]);
            __half2* dst = (__half2*)&g_xh[row * HC + col0 + c0];
            dst[0] = h01; dst[1] = h23;
        }
    }

    // fused attention coefficients: a = sum_c x[row,c]*att[h,c]
    float4 as = *(const float4*)&att_src[col0 + c0];
    float4 ad = *(const float4*)&att_dst[col0 + c0];
    #pragma unroll
    for (int i = 0; i < 4; i++) {
        float ps = acc[i][0] * as.x + acc[i][1] * as.y + acc[i][2] * as.z + acc[i][3] * as.w;
        float pd = acc[i][0] * ad.x + acc[i][1] * ad.y + acc[i][2] * ad.z + acc[i][3] * ad.w;
        #pragma unroll
        for (int off = 8; off > 0; off >>= 1) {
            ps += __shfl_down_sync(0xffffffffu, ps, off, 16);
            pd += __shfl_down_sync(0xffffffffu, pd, off, 16);
        }
        if (tx == 0) {
            int row = row0 + r0 + i;
            if (row < N) {
                g_asrc[row * 4 + hy] = ps;
                g_adst[row * 4 + hy] = pd;
            }
        }
    }
}

// ---------------- degree histogram + per-edge rank (decode dst only) ----------------
__global__ void degree_kernel(const int* __restrict__ e32, int N, int E) {
    int e = blockIdx.x * blockDim.x + threadIdx.x;
    int ET = E + N;
    if (e >= ET) return;
    int d;
    if (e < E) d = g_is64 ? e32[2 * E + 2 * e] : e32[E + e];
    else       d = e - E;
    g_rank[e] = atomicAdd(&g_deg[d], 1);
}

// ---------------- 3-kernel scan: deg -> exclusive offsets ----------------
__global__ void scan_local(int N) {     // grid: ceil(N/1024), block 1024
    __shared__ int wsum[32];
    int t = threadIdx.x, lane = t & 31, wid = t >> 5;
    int i = blockIdx.x * 1024 + t;
    int v = (i < N) ? g_deg[i] : 0;
    int x = v;
    #pragma unroll
    for (int o = 1; o < 32; o <<= 1) {
        int y = __shfl_up_sync(0xffffffffu, x, o);
        if (lane >= o) x += y;
    }
    if (lane == 31) wsum[wid] = x;
    __syncthreads();
    if (wid == 0) {
        int w = wsum[lane];
        #pragma unroll
        for (int o = 1; o < 32; o <<= 1) {
            int y = __shfl_up_sync(0xffffffffu, w, o);
            if (lane >= o) w += y;
        }
        wsum[lane] = w;
    }
    __syncthreads();
    int ex = (wid ? wsum[wid - 1] : 0) + x - v;
    if (i < N) g_off[i] = ex;
    if (t == 1023) g_bsum[blockIdx.x] = wsum[31];
}

__global__ void scan_blocks(int nb) {   // 1 block, 64 threads
    int t = threadIdx.x, lane = t & 31, wid = t >> 5;
    __shared__ int w0tot;
    int v = (t < nb) ? g_bsum[t] : 0;
    int x = v;
    #pragma unroll
    for (int o = 1; o < 32; o <<= 1) {
        int y = __shfl_up_sync(0xffffffffu, x, o);
        if (lane >= o) x += y;
    }
    if (wid == 0 && lane == 31) w0tot = x;
    __syncthreads();
    int ex = x - v + (wid ? w0tot : 0);
    if (t < nb) g_boff[t] = ex;
}

__global__ void scan_add(int N, int ET) {
    int i = blockIdx.x * 1024 + threadIdx.x;
    if (i < N) g_off[i] += g_boff[blockIdx.x];
    if (i == 0) g_off[N] = ET;
}

// ---------------- edge pass 2: decode, exp(leakyrelu), scatter packed rec (no atomics) ----------------
__global__ void edge_pass2(const int* __restrict__ e32, int N, int E) {
    int e = blockIdx.x * blockDim.x + threadIdx.x;
    int ET = E + N;
    if (e >= ET) return;
    int s, d;
    if (e < E) {
        if (g_is64) { s = e32[2 * e]; d = e32[2 * E + 2 * e]; }
        else        { s = e32[e];     d = e32[E + e]; }
    } else {
        s = d = e - E;
    }
    float4 as = *(const float4*)&g_asrc[s * 4];
    float4 ad = *(const float4*)&g_adst[d * 4];
    float l0 = as.x + ad.x, l1 = as.y + ad.y, l2 = as.z + ad.z, l3 = as.w + ad.w;
    l0 = l0 > 0.f ? l0 : 0.2f * l0;
    l1 = l1 > 0.f ? l1 : 0.2f * l1;
    l2 = l2 > 0.f ? l2 : 0.2f * l2;
    l3 = l3 > 0.f ? l3 : 0.2f * l3;
    __half2 e01 = __floats2half2_rn(__expf(l0), __expf(l1));
    __half2 e23 = __floats2half2_rn(__expf(l2), __expf(l3));
    float4 rec;
    rec.x = __int_as_float(s);
    rec.y = __uint_as_float(*(const unsigned int*)&e01);
    rec.z = __uint_as_float(*(const unsigned int*)&e23);
    rec.w = 0.0f;
    int pos = g_off[d] + g_rank[e];
    g_pack[pos] = rec;
}

// ---------------- warp-per-dst-node aggregation; segsum computed in-loop ----------------
__global__ void aggregate_kernel(const float* __restrict__ bias,
                                 float* __restrict__ out, int N) {
    int gw = (blockIdx.x * blockDim.x + threadIdx.x) >> 5;
    int lane = threadIdx.x & 31;
    if (gw >= N) return;
    int beg = g_off[gw], end = g_off[gw + 1];
    float a00 = 0.f, a01 = 0.f, a10 = 0.f, a11 = 0.f;
    float a20 = 0.f, a21 = 0.f, a30 = 0.f, a31 = 0.f;
    float s0 = 0.f, s1 = 0.f, s2 = 0.f, s3 = 0.f;
    for (int j = beg; j < end; j++) {
        float4 rec = g_pack[j];
        int s = __float_as_int(rec.x);
        unsigned int u01 = __float_as_uint(rec.y);
        unsigned int u23 = __float_as_uint(rec.z);
        float2 w01 = __half22float2(*(const __half2*)&u01);
        float2 w23 = __half22float2(*(const __half2*)&u23);
        const __half2* xr = (const __half2*)(g_xh + s * HC);
        float2 v0 = __half22float2(xr[lane]);
        float2 v1 = __half22float2(xr[32 + lane]);
        float2 v2 = __half22float2(xr[64 + lane]);
        float2 v3 = __half22float2(xr[96 + lane]);
        a00 += w01.x * v0.x; a01 += w01.x * v0.y;
        a10 += w01.y * v1.x; a11 += w01.y * v1.y;
        a20 += w23.x * v2.x; a21 += w23.x * v2.y;
        a30 += w23.y * v3.x; a31 += w23.y * v3.y;
        s0 += w01.x; s1 += w01.y; s2 += w23.x; s3 += w23.y;
    }
    float n0 = 0.25f / (s0 + 1e-16f);
    float n1 = 0.25f / (s1 + 1e-16f);
    float n2 = 0.25f / (s2 + 1e-16f);
    float n3 = 0.25f / (s3 + 1e-16f);
    int c = 2 * lane;
    float o0 = a00 * n0 + a10 * n1 + a20 * n2 + a30 * n3 + bias[c];
    float o1 = a01 * n0 + a11 * n1 + a21 * n2 + a31 * n3 + bias[c + 1];
    *(float2*)&out[gw * 64 + c] = make_float2(o0, o1);
}

// ---------------- launch ----------------
extern "C" void kernel_launch(void* const* d_in, const int* in_sizes, int n_in,
                              void* d_out, int out_size) {
    const float* meta_x  = (const float*)d_in[0];
    const int*   edge32  = (const int*)d_in[1];
    const float* W       = (const float*)d_in[2];
    const float* att_src = (const float*)d_in[3];
    const float* att_dst = (const float*)d_in[4];
    const float* bias    = (const float*)d_in[5];
    float*       out     = (float*)d_out;

    int N  = in_sizes[0] / 64;
    int E  = in_sizes[1] / 2;
    int ET = E + N;
    int nb = (N + 1023) / 1024;

    detect_kernel<<<1, 256>>>(edge32);
    init_kernel<<<(N + 255) / 256, 256>>>(N);
    gemm_kernel<<<dim3((N + 63) / 64, 4), 256>>>(meta_x, W, att_src, att_dst, N);
    degree_kernel<<<(ET + 255) / 256, 256>>>(edge32, N, E);
    scan_local<<<nb, 1024>>>(N);
    scan_blocks<<<1, 64>>>(nb);
    scan_add<<<nb, 1024>>>(N, ET);
    edge_pass2<<<(ET + 255) / 256, 256>>>(edge32, N, E);
    aggregate_kernel<<<(N * 32 + 255) / 256, 256>>>(bias, out, N);
}